// round 4
// baseline (speedup 1.0000x reference)
#include <cuda_runtime.h>
#include <stdint.h>

// Problem constants (fixed shapes for this problem)
#define BB 8
#define MM 1000000
#define NN (BB*MM)
#define GG 32                       // GRID/STRIDE = 128/4
#define NSEG (BB*GG*GG*GG)          // 262144 coarse blocks
#define PPB 4096                    // points per histogram block
#define NCHUNK ((MM + PPB - 1)/PPB) // 245
#define CAND_CAP (1<<20)            // >= MM: overflow impossible

// Scratch (static device allocations only)
__device__ unsigned g_bm[NSEG];        // per-block max (ordered-uint)
__device__ unsigned g_seg[NN];         // per-point segment id
__device__ unsigned g_key[NN];         // per-point masked ordered key
__device__ unsigned g_h1[BB*2048];
__device__ unsigned g_h2[BB*2048];
__device__ unsigned g_prefix[BB];      // 11-bit after pass1, 22-bit after pass2
__device__ unsigned g_krem[BB];
__device__ unsigned g_thr[BB];
__device__ unsigned g_ctr1[BB];
__device__ unsigned g_ctr2[BB];
__device__ unsigned g_ccount[BB];
__device__ unsigned g_cand[BB*CAND_CAP];

// Order-preserving float <-> uint bijection (total order, strict monotone)
__device__ __forceinline__ unsigned f2o(float f){
    unsigned b = __float_as_uint(f);
    return (b & 0x80000000u) ? ~b : (b | 0x80000000u);
}
__device__ __forceinline__ float o2f(unsigned u){
    return (u & 0x80000000u) ? __uint_as_float(u ^ 0x80000000u)
                             : __uint_as_float(~u);
}

#define INF_KEY 0xFF800000u  // f2o(+inf)

// In-block bin selection over a global 2048-bin histogram (L2 reads).
// Finds bin with cum < krem <= cum+c; writes prefix/krem (or thr if last).
__device__ void scan_tail_global(const unsigned* __restrict__ gh, int b,
                                 unsigned krem_in, unsigned pref_in, int shift){
    __shared__ unsigned partial[256];
    __shared__ unsigned excl[256];
    unsigned loc[8];
    unsigned s = 0;
    #pragma unroll
    for (int j = 0; j < 8; j++){ loc[j] = __ldcg(&gh[threadIdx.x*8 + j]); s += loc[j]; }
    partial[threadIdx.x] = s;
    __syncthreads();
    if (threadIdx.x == 0){
        unsigned c = 0;
        for (int t = 0; t < 256; t++){ unsigned v = partial[t]; excl[t] = c; c += v; }
    }
    __syncthreads();
    unsigned cum = excl[threadIdx.x];
    #pragma unroll
    for (int j = 0; j < 8; j++){
        unsigned bin = threadIdx.x*8 + j;
        unsigned c = loc[j];
        if (cum < krem_in && cum + c >= krem_in){
            g_prefix[b] = (pref_in << shift) | bin;
            g_krem[b]   = krem_in - cum;
        }
        cum += c;
    }
}

// ---------------------------------------------------------------- zero scratch
__global__ void k_zero(){
    int i = blockIdx.x*blockDim.x + threadIdx.x;
    int stride = gridDim.x*blockDim.x;
    for (int j = i; j < NSEG; j += stride) g_bm[j] = 0u;
    for (int j = i; j < BB*2048; j += stride){ g_h1[j] = 0u; g_h2[j] = 0u; }
    if (i < BB){ g_ctr1[i] = 0u; g_ctr2[i] = 0u; g_ccount[i] = 0u; }
}

// ------------------------------------------------- pass B: seg ids + block max
__global__ void k_blockmax(const float* __restrict__ pred,
                           const int4*  __restrict__ coords){
    int i = blockIdx.x*blockDim.x + threadIdx.x;
    int stride = gridDim.x*blockDim.x;
    for (int j = i; j < NN; j += stride){
        int4 c = coords[j];   // (batch, x, y, z)
        unsigned seg = ((((unsigned)c.x * GG + ((unsigned)c.y >> 2)) * GG
                         + ((unsigned)c.z >> 2)) * GG) + ((unsigned)c.w >> 2);
        g_seg[j] = seg;
        atomicMax(&g_bm[seg], f2o(pred[j]));
    }
}

// ---------- pass 1: masked keys + hist of top 11 key bits + fused scan tail
__global__ void k_key_hist(const float* __restrict__ pred,
                           const int* __restrict__ tnum){
    __shared__ unsigned sh[2048];
    __shared__ int isLast;
    for (int j = threadIdx.x; j < 2048; j += blockDim.x) sh[j] = 0u;
    __syncthreads();

    int b = blockIdx.y;
    int start = blockIdx.x * PPB;
    long base = (long)b * MM + start;          // divisible by 4
    const uint4*  s4 = (const uint4*)g_seg + (base >> 2);
    const float4* p4 = (const float4*)pred + (base >> 2);
    uint4*        k4 = (uint4*)g_key + (base >> 2);
    int nv = min(PPB, MM - start) >> 2;

    for (int v = threadIdx.x; v < nv; v += blockDim.x){
        uint4 s = s4[v];
        float4 p = p4[v];
        uint4 kk;
        kk.x = (p.x != o2f(g_bm[s.x])) ? f2o(p.x) : INF_KEY;
        kk.y = (p.y != o2f(g_bm[s.y])) ? f2o(p.y) : INF_KEY;
        kk.z = (p.z != o2f(g_bm[s.z])) ? f2o(p.z) : INF_KEY;
        kk.w = (p.w != o2f(g_bm[s.w])) ? f2o(p.w) : INF_KEY;
        k4[v] = kk;
        atomicAdd(&sh[kk.x >> 21], 1u);
        atomicAdd(&sh[kk.y >> 21], 1u);
        atomicAdd(&sh[kk.z >> 21], 1u);
        atomicAdd(&sh[kk.w >> 21], 1u);
    }
    __syncthreads();
    unsigned* gh = g_h1 + b*2048;
    for (int j = threadIdx.x; j < 2048; j += blockDim.x){
        unsigned c = sh[j];
        if (c) atomicAdd(&gh[j], c);
    }
    __threadfence();
    if (threadIdx.x == 0)
        isLast = (atomicAdd(&g_ctr1[b], 1u) == (unsigned)(NCHUNK - 1));
    __syncthreads();
    if (isLast)
        scan_tail_global(gh, b, (unsigned)(MM - tnum[0]), 0u, 0);
}

// ------- pass 2: hist bits [20:10] within bin1 + candidate compaction + scan
__global__ void k_hist2(){
    __shared__ unsigned sh[2048];
    __shared__ int isLast;
    for (int j = threadIdx.x; j < 2048; j += blockDim.x) sh[j] = 0u;
    __syncthreads();

    int b = blockIdx.y;
    unsigned p = g_prefix[b];                  // 11-bit prefix
    int start = blockIdx.x * PPB;
    long base = (long)b * MM + start;
    const uint4* k4 = (const uint4*)g_key + (base >> 2);
    int nv = min(PPB, MM - start) >> 2;
    unsigned* cand = g_cand + (size_t)b * CAND_CAP;

    for (int v = threadIdx.x; v < nv; v += blockDim.x){
        uint4 kk = k4[v];
        if ((kk.x >> 21) == p){ atomicAdd(&sh[(kk.x >> 10) & 2047u], 1u);
                                cand[atomicAdd(&g_ccount[b], 1u)] = kk.x; }
        if ((kk.y >> 21) == p){ atomicAdd(&sh[(kk.y >> 10) & 2047u], 1u);
                                cand[atomicAdd(&g_ccount[b], 1u)] = kk.y; }
        if ((kk.z >> 21) == p){ atomicAdd(&sh[(kk.z >> 10) & 2047u], 1u);
                                cand[atomicAdd(&g_ccount[b], 1u)] = kk.z; }
        if ((kk.w >> 21) == p){ atomicAdd(&sh[(kk.w >> 10) & 2047u], 1u);
                                cand[atomicAdd(&g_ccount[b], 1u)] = kk.w; }
    }
    __syncthreads();
    unsigned* gh = g_h2 + b*2048;
    for (int j = threadIdx.x; j < 2048; j += blockDim.x){
        unsigned c = sh[j];
        if (c) atomicAdd(&gh[j], c);
    }
    __threadfence();
    if (threadIdx.x == 0)
        isLast = (atomicAdd(&g_ctr2[b], 1u) == (unsigned)(NCHUNK - 1));
    __syncthreads();
    if (isLast)
        scan_tail_global(gh, b, g_krem[b], p, 11);
}

// ------ pass 3: candidates only (one block per batch), in-shared hist + scan
__global__ void k_hist3(){
    __shared__ unsigned sh[1024];
    __shared__ unsigned partial[256];
    __shared__ unsigned excl[256];
    int b = blockIdx.x;
    for (int j = threadIdx.x; j < 1024; j += blockDim.x) sh[j] = 0u;
    __syncthreads();

    unsigned p = g_prefix[b];                  // 22-bit prefix
    unsigned n = min(g_ccount[b], (unsigned)CAND_CAP);
    const unsigned* cand = g_cand + (size_t)b * CAND_CAP;
    for (unsigned i = threadIdx.x; i < n; i += blockDim.x){
        unsigned k = __ldcg(&cand[i]);
        if ((k >> 10) == p) atomicAdd(&sh[k & 1023u], 1u);
    }
    __syncthreads();

    unsigned loc[4];
    unsigned s = 0;
    #pragma unroll
    for (int j = 0; j < 4; j++){ loc[j] = sh[threadIdx.x*4 + j]; s += loc[j]; }
    partial[threadIdx.x] = s;
    __syncthreads();
    if (threadIdx.x == 0){
        unsigned c = 0;
        for (int t = 0; t < 256; t++){ unsigned v = partial[t]; excl[t] = c; c += v; }
    }
    __syncthreads();
    unsigned krem = g_krem[b];
    unsigned cum = excl[threadIdx.x];
    #pragma unroll
    for (int j = 0; j < 4; j++){
        unsigned bin = threadIdx.x*4 + j;
        unsigned c = loc[j];
        if (cum < krem && cum + c >= krem)
            g_thr[b] = (p << 10) | bin;        // exact kth-smallest key
        cum += c;
    }
}

// -------------------------------------------------------- final masked output
__global__ void k_out(const float* __restrict__ pred, float* __restrict__ out){
    int v = blockIdx.x*blockDim.x + threadIdx.x;   // vector index, NN/4 total
    if (v >= NN/4) return;
    int b = v / (MM/4);
    unsigned thr = g_thr[b];
    uint4 kk = ((const uint4*)g_key)[v];
    float4 p = ((const float4*)pred)[v];
    float4 o;
    o.x = (kk.x > thr) ? p.x : 0.0f;
    o.y = (kk.y > thr) ? p.y : 0.0f;
    o.z = (kk.z > thr) ? p.z : 0.0f;
    o.w = (kk.w > thr) ? p.w : 0.0f;
    ((float4*)out)[v] = o;
}

extern "C" void kernel_launch(void* const* d_in, const int* in_sizes, int n_in,
                              void* d_out, int out_size){
    const float* pred   = (const float*)d_in[0];
    const int4*  coords = (const int4*)d_in[1];
    const int*   tnum   = (const int*)d_in[2];
    float* out = (float*)d_out;

    k_zero<<<1024, 256>>>();
    k_blockmax<<<(NN + 511)/512, 256>>>(pred, coords);

    dim3 gh(NCHUNK, BB);
    k_key_hist<<<gh, 256>>>(pred, tnum);
    k_hist2<<<gh, 256>>>();
    k_hist3<<<BB, 256>>>();

    k_out<<<(NN/4 + 255)/256, 256>>>(pred, out);
}

// round 5
// speedup vs baseline: 1.5191x; 1.5191x over previous
#include <cuda_runtime.h>
#include <stdint.h>

// Problem constants (fixed shapes for this problem)
#define BB 8
#define MM 1000000
#define NN (BB*MM)
#define GG 32                       // GRID/STRIDE = 128/4
#define NSEG (BB*GG*GG*GG)          // 262144 coarse blocks
#define PPB 4096                    // points per histogram block
#define NCHUNK ((MM + PPB - 1)/PPB) // 245
#define CAND_CAP (1<<20)            // >= MM: overflow impossible

// Scratch (static device allocations only)
__device__ unsigned g_bm[NSEG];        // per-block max (ordered-uint)
__device__ unsigned g_seg[NN];         // per-point segment id
__device__ unsigned g_key[NN];         // per-point masked ordered key
__device__ unsigned g_h1[BB*2048];
__device__ unsigned g_h2[BB*2048];
__device__ unsigned g_prefix[BB];      // 11-bit after pass1, 22-bit after pass2
__device__ unsigned g_krem[BB];
__device__ unsigned g_thr[BB];
__device__ unsigned g_ctr1[BB];
__device__ unsigned g_ctr2[BB];
__device__ unsigned g_ccount[BB];
__device__ unsigned g_cand[BB*CAND_CAP];

// Order-preserving float <-> uint bijection (total order, strict monotone)
__device__ __forceinline__ unsigned f2o(float f){
    unsigned b = __float_as_uint(f);
    return (b & 0x80000000u) ? ~b : (b | 0x80000000u);
}
__device__ __forceinline__ float o2f(unsigned u){
    return (u & 0x80000000u) ? __uint_as_float(u ^ 0x80000000u)
                             : __uint_as_float(~u);
}

#define INF_KEY 0xFF800000u  // f2o(+inf)

// In-block bin selection over a global 2048-bin histogram (L2 reads).
// Finds bin with cum < krem <= cum+c; writes prefix/krem.
__device__ void scan_tail_global(const unsigned* __restrict__ gh, int b,
                                 unsigned krem_in, unsigned pref_in, int shift){
    __shared__ unsigned partial[256];
    __shared__ unsigned excl[256];
    unsigned loc[8];
    unsigned s = 0;
    #pragma unroll
    for (int j = 0; j < 8; j++){ loc[j] = __ldcg(&gh[threadIdx.x*8 + j]); s += loc[j]; }
    partial[threadIdx.x] = s;
    __syncthreads();
    if (threadIdx.x == 0){
        unsigned c = 0;
        for (int t = 0; t < 256; t++){ unsigned v = partial[t]; excl[t] = c; c += v; }
    }
    __syncthreads();
    unsigned cum = excl[threadIdx.x];
    #pragma unroll
    for (int j = 0; j < 8; j++){
        unsigned bin = threadIdx.x*8 + j;
        unsigned c = loc[j];
        if (cum < krem_in && cum + c >= krem_in){
            g_prefix[b] = (pref_in << shift) | bin;
            g_krem[b]   = krem_in - cum;
        }
        cum += c;
    }
}

// ---------------------------------------------------------------- zero scratch
__global__ void k_zero(){
    int i = blockIdx.x*blockDim.x + threadIdx.x;
    int stride = gridDim.x*blockDim.x;
    for (int j = i; j < NSEG; j += stride) g_bm[j] = 0u;
    for (int j = i; j < BB*2048; j += stride){ g_h1[j] = 0u; g_h2[j] = 0u; }
    if (i < BB){ g_ctr1[i] = 0u; g_ctr2[i] = 0u; g_ccount[i] = 0u; }
}

// ------------------------------------------------- pass B: seg ids + block max
__global__ void k_blockmax(const float* __restrict__ pred,
                           const int4*  __restrict__ coords){
    int i = blockIdx.x*blockDim.x + threadIdx.x;
    int stride = gridDim.x*blockDim.x;
    for (int j = i; j < NN; j += stride){
        int4 c = coords[j];   // (batch, x, y, z)
        unsigned seg = ((((unsigned)c.x * GG + ((unsigned)c.y >> 2)) * GG
                         + ((unsigned)c.z >> 2)) * GG) + ((unsigned)c.w >> 2);
        __stcs(&g_seg[j], seg);                // streaming: keep L2 for g_bm
        atomicMax(&g_bm[seg], f2o(pred[j]));
    }
}

// ---------- pass 1: masked keys + hist of top 11 key bits + fused scan tail
__global__ void k_key_hist(const float* __restrict__ pred,
                           const int* __restrict__ tnum){
    __shared__ unsigned sh[2048];
    __shared__ int isLast;
    for (int j = threadIdx.x; j < 2048; j += blockDim.x) sh[j] = 0u;
    __syncthreads();

    int b = blockIdx.y;
    int start = blockIdx.x * PPB;
    long base = (long)b * MM + start;          // divisible by 4
    const uint4*  s4 = (const uint4*)g_seg + (base >> 2);
    const float4* p4 = (const float4*)pred + (base >> 2);
    uint4*        k4 = (uint4*)g_key + (base >> 2);
    int nv = min(PPB, MM - start) >> 2;

    for (int v = threadIdx.x; v < nv; v += blockDim.x){
        uint4 s = __ldcs(&s4[v]);
        float4 p = p4[v];
        uint4 kk;
        kk.x = (p.x != o2f(g_bm[s.x])) ? f2o(p.x) : INF_KEY;
        kk.y = (p.y != o2f(g_bm[s.y])) ? f2o(p.y) : INF_KEY;
        kk.z = (p.z != o2f(g_bm[s.z])) ? f2o(p.z) : INF_KEY;
        kk.w = (p.w != o2f(g_bm[s.w])) ? f2o(p.w) : INF_KEY;
        __stcs(&k4[v], kk);
        atomicAdd(&sh[kk.x >> 21], 1u);
        atomicAdd(&sh[kk.y >> 21], 1u);
        atomicAdd(&sh[kk.z >> 21], 1u);
        atomicAdd(&sh[kk.w >> 21], 1u);
    }
    __syncthreads();
    unsigned* gh = g_h1 + b*2048;
    for (int j = threadIdx.x; j < 2048; j += blockDim.x){
        unsigned c = sh[j];
        if (c) atomicAdd(&gh[j], c);
    }
    __threadfence();
    if (threadIdx.x == 0)
        isLast = (atomicAdd(&g_ctr1[b], 1u) == (unsigned)(NCHUNK - 1));
    __syncthreads();
    if (isLast)
        scan_tail_global(gh, b, (unsigned)(MM - tnum[0]), 0u, 0);
}

// ------- pass 2: hist bits [20:10] within bin1 + block-staged compaction
__global__ void k_hist2(){
    __shared__ unsigned sh[2048];
    __shared__ unsigned stage[PPB];            // worst case: every element matches
    __shared__ unsigned scount, sbase;
    __shared__ int isLast;
    for (int j = threadIdx.x; j < 2048; j += blockDim.x) sh[j] = 0u;
    if (threadIdx.x == 0) scount = 0u;
    __syncthreads();

    int b = blockIdx.y;
    unsigned p = g_prefix[b];                  // 11-bit prefix
    int start = blockIdx.x * PPB;
    long base = (long)b * MM + start;
    const uint4* k4 = (const uint4*)g_key + (base >> 2);
    int nv = min(PPB, MM - start) >> 2;

    for (int v = threadIdx.x; v < nv; v += blockDim.x){
        uint4 kk = __ldcs(&k4[v]);
        if ((kk.x >> 21) == p){ atomicAdd(&sh[(kk.x >> 10) & 2047u], 1u);
                                stage[atomicAdd(&scount, 1u)] = kk.x; }
        if ((kk.y >> 21) == p){ atomicAdd(&sh[(kk.y >> 10) & 2047u], 1u);
                                stage[atomicAdd(&scount, 1u)] = kk.y; }
        if ((kk.z >> 21) == p){ atomicAdd(&sh[(kk.z >> 10) & 2047u], 1u);
                                stage[atomicAdd(&scount, 1u)] = kk.z; }
        if ((kk.w >> 21) == p){ atomicAdd(&sh[(kk.w >> 10) & 2047u], 1u);
                                stage[atomicAdd(&scount, 1u)] = kk.w; }
    }
    __syncthreads();

    // one global reservation per block, then coalesced flush of candidates
    if (threadIdx.x == 0) sbase = atomicAdd(&g_ccount[b], scount);
    __syncthreads();
    unsigned* cand = g_cand + (size_t)b * CAND_CAP;
    for (unsigned i = threadIdx.x; i < scount; i += blockDim.x)
        __stcg(&cand[sbase + i], stage[i]);

    unsigned* gh = g_h2 + b*2048;
    for (int j = threadIdx.x; j < 2048; j += blockDim.x){
        unsigned c = sh[j];
        if (c) atomicAdd(&gh[j], c);
    }
    __threadfence();
    if (threadIdx.x == 0)
        isLast = (atomicAdd(&g_ctr2[b], 1u) == (unsigned)(NCHUNK - 1));
    __syncthreads();
    if (isLast)
        scan_tail_global(gh, b, g_krem[b], p, 11);
}

// ------ pass 3: candidates only (one block per batch), in-shared hist + scan
__global__ void k_hist3(){
    __shared__ unsigned sh[1024];
    __shared__ unsigned partial[256];
    __shared__ unsigned excl[256];
    int b = blockIdx.x;
    for (int j = threadIdx.x; j < 1024; j += blockDim.x) sh[j] = 0u;
    __syncthreads();

    unsigned p = g_prefix[b];                  // 22-bit prefix
    unsigned n = min(g_ccount[b], (unsigned)CAND_CAP);
    const unsigned* cand = g_cand + (size_t)b * CAND_CAP;
    for (unsigned i = threadIdx.x; i < n; i += blockDim.x){
        unsigned k = __ldcg(&cand[i]);
        if ((k >> 10) == p) atomicAdd(&sh[k & 1023u], 1u);
    }
    __syncthreads();

    unsigned loc[4];
    unsigned s = 0;
    #pragma unroll
    for (int j = 0; j < 4; j++){ loc[j] = sh[threadIdx.x*4 + j]; s += loc[j]; }
    partial[threadIdx.x] = s;
    __syncthreads();
    if (threadIdx.x == 0){
        unsigned c = 0;
        for (int t = 0; t < 256; t++){ unsigned v = partial[t]; excl[t] = c; c += v; }
    }
    __syncthreads();
    unsigned krem = g_krem[b];
    unsigned cum = excl[threadIdx.x];
    #pragma unroll
    for (int j = 0; j < 4; j++){
        unsigned bin = threadIdx.x*4 + j;
        unsigned c = loc[j];
        if (cum < krem && cum + c >= krem)
            g_thr[b] = (p << 10) | bin;        // exact kth-smallest key
        cum += c;
    }
}

// -------------------------------------------------------- final masked output
__global__ void k_out(const float* __restrict__ pred, float* __restrict__ out){
    int v = blockIdx.x*blockDim.x + threadIdx.x;   // vector index, NN/4 total
    if (v >= NN/4) return;
    int b = v / (MM/4);
    unsigned thr = g_thr[b];
    uint4 kk = __ldcs(&((const uint4*)g_key)[v]);
    float4 p = ((const float4*)pred)[v];
    float4 o;
    o.x = (kk.x > thr) ? p.x : 0.0f;
    o.y = (kk.y > thr) ? p.y : 0.0f;
    o.z = (kk.z > thr) ? p.z : 0.0f;
    o.w = (kk.w > thr) ? p.w : 0.0f;
    __stcs(&((float4*)out)[v], o);
}

extern "C" void kernel_launch(void* const* d_in, const int* in_sizes, int n_in,
                              void* d_out, int out_size){
    const float* pred   = (const float*)d_in[0];
    const int4*  coords = (const int4*)d_in[1];
    const int*   tnum   = (const int*)d_in[2];
    float* out = (float*)d_out;

    k_zero<<<1024, 256>>>();
    k_blockmax<<<(NN + 511)/512, 256>>>(pred, coords);

    dim3 gh(NCHUNK, BB);
    k_key_hist<<<gh, 256>>>(pred, tnum);
    k_hist2<<<gh, 256>>>();
    k_hist3<<<BB, 256>>>();

    k_out<<<(NN/4 + 255)/256, 256>>>(pred, out);
}

// round 7
// speedup vs baseline: 1.5616x; 1.0280x over previous
#include <cuda_runtime.h>
#include <stdint.h>

// Problem constants (fixed shapes for this problem)
#define BB 8
#define MM 1000000
#define NN (BB*MM)
#define GG 32                       // GRID/STRIDE = 128/4
#define SEGB (GG*GG*GG)             // 32768 blocks per batch (fits uint16)
#define NSEG (BB*SEGB)              // 262144 coarse blocks
#define PPB 4096                    // points per histogram block
#define NCHUNK ((MM + PPB - 1)/PPB) // 245
#define CAND_CAP (1<<20)            // >= MM: overflow impossible

// Scratch (static device allocations only)
__device__ unsigned g_bm[NSEG];          // per-block max (ordered-uint)
__device__ unsigned short g_seg16[NN];   // per-point seg-within-batch
__device__ unsigned g_mask[NN/32];       // 1 bit per point: is local max
__device__ unsigned g_h1[BB*2048];
__device__ unsigned g_h2[BB*2048];
__device__ unsigned g_prefix[BB];        // 11-bit after pass1, 22-bit after pass2
__device__ unsigned g_krem[BB];
__device__ unsigned g_thr[BB];
__device__ unsigned g_ctr1[BB];
__device__ unsigned g_ctr2[BB];
__device__ unsigned g_ccount[BB];
__device__ unsigned g_cand[BB*CAND_CAP];

// Order-preserving float <-> uint bijection (total order, strict monotone)
__device__ __forceinline__ unsigned f2o(float f){
    unsigned b = __float_as_uint(f);
    return (b & 0x80000000u) ? ~b : (b | 0x80000000u);
}

#define INF_KEY 0xFF800000u  // f2o(+inf); top-11 bits = 0x7FC (never a selectable prefix)

// In-block bin selection over a global 2048-bin histogram (L2 reads).
__device__ void scan_tail_global(const unsigned* __restrict__ gh, int b,
                                 unsigned krem_in, unsigned pref_in, int shift){
    __shared__ unsigned partial[256];
    __shared__ unsigned excl[256];
    unsigned loc[8];
    unsigned s = 0;
    #pragma unroll
    for (int j = 0; j < 8; j++){ loc[j] = __ldcg(&gh[threadIdx.x*8 + j]); s += loc[j]; }
    partial[threadIdx.x] = s;
    __syncthreads();
    if (threadIdx.x == 0){
        unsigned c = 0;
        for (int t = 0; t < 256; t++){ unsigned v = partial[t]; excl[t] = c; c += v; }
    }
    __syncthreads();
    unsigned cum = excl[threadIdx.x];
    #pragma unroll
    for (int j = 0; j < 8; j++){
        unsigned bin = threadIdx.x*8 + j;
        unsigned c = loc[j];
        if (cum < krem_in && cum + c >= krem_in){
            g_prefix[b] = (pref_in << shift) | bin;
            g_krem[b]   = krem_in - cum;
        }
        cum += c;
    }
}

// ---------------------------------------------------------------- zero scratch
__global__ void k_zero(){
    int i = blockIdx.x*blockDim.x + threadIdx.x;
    int stride = gridDim.x*blockDim.x;
    for (int j = i; j < NSEG; j += stride) g_bm[j] = 0u;
    for (int j = i; j < BB*2048; j += stride){ g_h1[j] = 0u; g_h2[j] = 0u; }
    if (i < BB){ g_ctr1[i] = 0u; g_ctr2[i] = 0u; g_ccount[i] = 0u; }
}

// ------------------------------------------------- pass B: seg ids + block max
__global__ void k_blockmax(const float* __restrict__ pred,
                           const int4*  __restrict__ coords){
    int i = blockIdx.x*blockDim.x + threadIdx.x;
    int stride = gridDim.x*blockDim.x;
    for (int j = i; j < NN; j += stride){
        int4 c = coords[j];   // (batch, x, y, z)
        unsigned local = (((unsigned)c.y >> 2) * GG + ((unsigned)c.z >> 2)) * GG
                         + ((unsigned)c.w >> 2);
        g_seg16[j] = (unsigned short)local;
        atomicMax(&g_bm[(unsigned)c.x * SEGB + local], f2o(pred[j]));
    }
}

// ----- pass 1: local-max bitmap + hist of top 11 key bits + fused scan tail
__global__ void k_mask_hist(const float* __restrict__ pred,
                            const int* __restrict__ tnum){
    __shared__ unsigned sh[2048];
    __shared__ unsigned smb[PPB/32];          // 128 bitmap words for this tile
    __shared__ int isLast;
    for (int j = threadIdx.x; j < 2048; j += blockDim.x) sh[j] = 0u;
    if (threadIdx.x < PPB/32) smb[threadIdx.x] = 0u;
    __syncthreads();

    int b = blockIdx.y;
    int start = blockIdx.x * PPB;
    long base = (long)b * MM + start;          // divisible by 4096 (except tail ok)
    const ushort4* s4 = (const ushort4*)g_seg16 + (base >> 2);
    const float4*  p4 = (const float4*)pred + (base >> 2);
    const unsigned* bmb = g_bm + b * SEGB;
    int nv = min(PPB, MM - start) >> 2;

    for (int v = threadIdx.x; v < nv; v += blockDim.x){
        ushort4 s = s4[v];
        float4 p = p4[v];
        unsigned fx = f2o(p.x), fy = f2o(p.y), fz = f2o(p.z), fw = f2o(p.w);
        unsigned mx = (fx == bmb[s.x]);
        unsigned my = (fy == bmb[s.y]);
        unsigned mz = (fz == bmb[s.z]);
        unsigned mw = (fw == bmb[s.w]);
        atomicAdd(&sh[(mx ? INF_KEY : fx) >> 21], 1u);
        atomicAdd(&sh[(my ? INF_KEY : fy) >> 21], 1u);
        atomicAdd(&sh[(mz ? INF_KEY : fz) >> 21], 1u);
        atomicAdd(&sh[(mw ? INF_KEY : fw) >> 21], 1u);
        unsigned nib = mx | (my << 1) | (mz << 2) | (mw << 3);
        if (nib) atomicOr(&smb[v >> 3], nib << ((v & 7) * 4));
    }
    __syncthreads();

    // flush ONLY the words owned by this tile (fix: last chunk of a batch must
    // not write past its batch boundary into the next batch's mask region)
    int nwords = (nv + 7) >> 3;
    unsigned* gw = g_mask + (base >> 5);
    if (threadIdx.x < nwords) gw[threadIdx.x] = smb[threadIdx.x];

    unsigned* gh = g_h1 + b*2048;
    for (int j = threadIdx.x; j < 2048; j += blockDim.x){
        unsigned c = sh[j];
        if (c) atomicAdd(&gh[j], c);
    }
    __threadfence();
    if (threadIdx.x == 0)
        isLast = (atomicAdd(&g_ctr1[b], 1u) == (unsigned)(NCHUNK - 1));
    __syncthreads();
    if (isLast)
        scan_tail_global(gh, b, (unsigned)(MM - tnum[0]), 0u, 0);
}

// ------- pass 2: hist bits [20:10] within bin1 + block-staged compaction
__global__ void k_hist2(const float* __restrict__ pred){
    __shared__ unsigned sh[2048];
    __shared__ unsigned stage[PPB];            // worst case: every element matches
    __shared__ unsigned scount, sbase;
    __shared__ int isLast;
    for (int j = threadIdx.x; j < 2048; j += blockDim.x) sh[j] = 0u;
    if (threadIdx.x == 0) scount = 0u;
    __syncthreads();

    int b = blockIdx.y;
    unsigned p = g_prefix[b];                  // 11-bit prefix
    int start = blockIdx.x * PPB;
    long base = (long)b * MM + start;
    const float4* p4 = (const float4*)pred + (base >> 2);
    const unsigned* gw = g_mask + (base >> 5);
    int nv = min(PPB, MM - start) >> 2;

    for (int v = threadIdx.x; v < nv; v += blockDim.x){
        float4 pv = p4[v];
        unsigned nib = (__ldcg(&gw[v >> 3]) >> ((v & 7) * 4)) & 0xFu;
        unsigned fx = f2o(pv.x), fy = f2o(pv.y), fz = f2o(pv.z), fw = f2o(pv.w);
        if (!(nib & 1u) && (fx >> 21) == p){ atomicAdd(&sh[(fx >> 10) & 2047u], 1u);
                                             stage[atomicAdd(&scount, 1u)] = fx; }
        if (!(nib & 2u) && (fy >> 21) == p){ atomicAdd(&sh[(fy >> 10) & 2047u], 1u);
                                             stage[atomicAdd(&scount, 1u)] = fy; }
        if (!(nib & 4u) && (fz >> 21) == p){ atomicAdd(&sh[(fz >> 10) & 2047u], 1u);
                                             stage[atomicAdd(&scount, 1u)] = fz; }
        if (!(nib & 8u) && (fw >> 21) == p){ atomicAdd(&sh[(fw >> 10) & 2047u], 1u);
                                             stage[atomicAdd(&scount, 1u)] = fw; }
    }
    __syncthreads();

    // one global reservation per block, then coalesced flush of candidates
    if (threadIdx.x == 0) sbase = atomicAdd(&g_ccount[b], scount);
    __syncthreads();
    unsigned* cand = g_cand + (size_t)b * CAND_CAP;
    for (unsigned i = threadIdx.x; i < scount; i += blockDim.x)
        __stcg(&cand[sbase + i], stage[i]);

    unsigned* gh = g_h2 + b*2048;
    for (int j = threadIdx.x; j < 2048; j += blockDim.x){
        unsigned c = sh[j];
        if (c) atomicAdd(&gh[j], c);
    }
    __threadfence();
    if (threadIdx.x == 0)
        isLast = (atomicAdd(&g_ctr2[b], 1u) == (unsigned)(NCHUNK - 1));
    __syncthreads();
    if (isLast)
        scan_tail_global(gh, b, g_krem[b], p, 11);
}

// ------ pass 3: candidates only (one block per batch), in-shared hist + scan
__global__ void k_hist3(){
    __shared__ unsigned sh[1024];
    __shared__ unsigned partial[256];
    __shared__ unsigned excl[256];
    int b = blockIdx.x;
    for (int j = threadIdx.x; j < 1024; j += blockDim.x) sh[j] = 0u;
    __syncthreads();

    unsigned p = g_prefix[b];                  // 22-bit prefix
    unsigned n = min(g_ccount[b], (unsigned)CAND_CAP);
    const unsigned* cand = g_cand + (size_t)b * CAND_CAP;
    for (unsigned i = threadIdx.x; i < n; i += blockDim.x){
        unsigned k = __ldcg(&cand[i]);
        if ((k >> 10) == p) atomicAdd(&sh[k & 1023u], 1u);
    }
    __syncthreads();

    unsigned loc[4];
    unsigned s = 0;
    #pragma unroll
    for (int j = 0; j < 4; j++){ loc[j] = sh[threadIdx.x*4 + j]; s += loc[j]; }
    partial[threadIdx.x] = s;
    __syncthreads();
    if (threadIdx.x == 0){
        unsigned c = 0;
        for (int t = 0; t < 256; t++){ unsigned v = partial[t]; excl[t] = c; c += v; }
    }
    __syncthreads();
    unsigned krem = g_krem[b];
    unsigned cum = excl[threadIdx.x];
    #pragma unroll
    for (int j = 0; j < 4; j++){
        unsigned bin = threadIdx.x*4 + j;
        unsigned c = loc[j];
        if (cum < krem && cum + c >= krem)
            g_thr[b] = (p << 10) | bin;        // exact kth-smallest key
        cum += c;
    }
}

// -------------------------------------------------------- final masked output
__global__ void k_out(const float* __restrict__ pred, float* __restrict__ out){
    int v = blockIdx.x*blockDim.x + threadIdx.x;   // vector index, NN/4 total
    if (v >= NN/4) return;
    int b = v / (MM/4);
    unsigned thr = g_thr[b];
    unsigned nib = (__ldcg(&g_mask[v >> 3]) >> ((v & 7) * 4)) & 0xFu;
    float4 p = ((const float4*)pred)[v];
    float4 o;
    o.x = ((nib & 1u) || f2o(p.x) > thr) ? p.x : 0.0f;
    o.y = ((nib & 2u) || f2o(p.y) > thr) ? p.y : 0.0f;
    o.z = ((nib & 4u) || f2o(p.z) > thr) ? p.z : 0.0f;
    o.w = ((nib & 8u) || f2o(p.w) > thr) ? p.w : 0.0f;
    __stcs(&((float4*)out)[v], o);
}

extern "C" void kernel_launch(void* const* d_in, const int* in_sizes, int n_in,
                              void* d_out, int out_size){
    const float* pred   = (const float*)d_in[0];
    const int4*  coords = (const int4*)d_in[1];
    const int*   tnum   = (const int*)d_in[2];
    float* out = (float*)d_out;

    k_zero<<<512, 256>>>();
    k_blockmax<<<(NN + 511)/512, 256>>>(pred, coords);

    dim3 gh(NCHUNK, BB);
    k_mask_hist<<<gh, 256>>>(pred, tnum);
    k_hist2<<<gh, 256>>>(pred);
    k_hist3<<<BB, 256>>>();

    k_out<<<(NN/4 + 255)/256, 256>>>(pred, out);
}